// round 16
// baseline (speedup 1.0000x reference)
#include <cuda_runtime.h>
#include <math.h>

#define NN 4
#define CC 26
#define NC 104
#define HH 512
#define WW 512
#define PH 171
#define PW 171
#define IMG (PH*PW)     // 29241
#define NY 169
#define NX 169
#define MTOT (NY*NX)
#define PRB 2           // pool: output rows per block
#define RSTR 520        // pool: smem row stride (4 pad + 512 + 4)
#define RB 29           // gram: image rows per band
#define NBANDS 6        // ceil(171/29)
#define GSTR 176        // gram smem col stride (2 pad + 171 + 3 pad)

typedef unsigned long long ull;

// scratch (static device arrays; no runtime allocation)
__device__ float g_pla[NC*IMG];        // pooled labels, SHIFTED by -0.5
__device__ float g_ppr[NC*IMG];        // pooled probs,  SHIFTED by -0.5
__device__ float g_part2[NC*NBANDS*64];// per-band lag partials (53 used)
__device__ double g_rmi[NC];
__device__ int    g_cnt = 0;

// ---- f32x2 packed helpers (sm_103a FFMA2 via PTX) -------------------------
__device__ __forceinline__ ull pk2(float lo, float hi) {
    ull r; asm("mov.b64 %0,{%1,%2};" : "=l"(r) : "f"(lo), "f"(hi)); return r;
}
__device__ __forceinline__ void fma2(ull& acc, ull a, ull b) {
    asm("fma.rn.f32x2 %0,%1,%2,%0;" : "+l"(acc) : "l"(a), "l"(b));
}
__device__ __forceinline__ void add2(ull& acc, ull v) {
    asm("add.rn.f32x2 %0,%1,%0;" : "+l"(acc) : "l"(v));
}
__device__ __forceinline__ void upk2(ull v, float& lo, float& hi) {
    asm("mov.b64 {%0,%1},%2;" : "=f"(lo), "=f"(hi) : "l"(v));
}
__device__ __forceinline__ int tri_idx(int i, int j)  // i <= j, 18x18 upper tri
{
    return i*18 - (i*(i-1))/2 + (j - i);
}
// canonical lag list (a,b): a=0:b in 0..2 -> k=b; a=1:b in -2..2 -> k=5+b; a=2 -> k=10+b
__device__ __forceinline__ int lag_k(int a, int b)
{
    return (a == 0) ? b : ((a == 1) ? 5 + b : 10 + b);
}
// strip index maps (valid only for u/v in {0..3} U {165..170})
__device__ __forceinline__ int rmap(int u) { return (u < 4) ? u : u - 161; }

// ---------------------------------------------------------------------------
// Kernel 1: mask + sigmoid + 3x3/stride3 max-pool, smem-staged.
// Writes planes shifted by -0.5 (covariances are shift-invariant).
// ---------------------------------------------------------------------------
__global__ __launch_bounds__(256) void pool_kernel(const float* __restrict__ cls,
                                                   const float* __restrict__ tgt,
                                                   const float* __restrict__ valid)
{
    int nc  = blockIdx.y;
    int n   = nc / CC;
    int py0 = blockIdx.x * PRB;
    int t   = threadIdx.x;

    __shared__ float sT[6*RSTR];
    __shared__ float sX[6*RSTR];

    const float* cb = cls   + (size_t)nc * HH * WW;
    const float* tb = tgt   + (size_t)nc * HH * WW;
    const float* vb = valid + (size_t)n  * HH * WW;

    const float BIG = -3.0e38f;

    for (int q = t; q < 6*128; q += 256) {
        int i = q >> 7;
        int k = q & 127;
        int r = 3*py0 - 1 + i;
        float4 T4, X4;
        if ((unsigned)r < (unsigned)HH) {
            float4 c = ((const float4*)(cb + (size_t)r*WW))[k];
            float4 g = ((const float4*)(tb + (size_t)r*WW))[k];
            float4 v = ((const float4*)(vb + (size_t)r*WW))[k];
            T4.x = g.x*v.x; T4.y = g.y*v.y; T4.z = g.z*v.z; T4.w = g.w*v.w;
            X4.x = v.x > 0.0f ? c.x : BIG;
            X4.y = v.y > 0.0f ? c.y : BIG;
            X4.z = v.z > 0.0f ? c.z : BIG;
            X4.w = v.w > 0.0f ? c.w : BIG;
        } else {
            T4.x = T4.y = T4.z = T4.w = 0.0f;
            X4.x = X4.y = X4.z = X4.w = BIG;
        }
        *(float4*)&sT[i*RSTR + 4 + 4*k] = T4;
        *(float4*)&sX[i*RSTR + 4 + 4*k] = X4;
    }
    if (t < 6) { sT[t*RSTR + 3] = 0.0f; sX[t*RSTR + 3] = BIG; }
    __syncthreads();

    for (int o = t; o < PRB*PW; o += 256) {
        int pyl = o / PW, px = o - pyl*PW;
        int py  = py0 + pyl;
        if (py >= PH) continue;
        int base = pyl*3*RSTR + 3 + 3*px;
        float mla = 0.0f, mx = BIG;
        #pragma unroll
        for (int rr = 0; rr < 3; rr++) {
            int bb = base + rr*RSTR;
            #pragma unroll
            for (int cc = 0; cc < 3; cc++) {
                mla = fmaxf(mla, sT[bb + cc]);
                mx  = fmaxf(mx,  sX[bb + cc]);
            }
        }
        float pp = 1.0f/(1.0f + __expf(-mx)) + 1e-6f;
        size_t ob = (size_t)nc * IMG + (size_t)py*PW + px;
        g_pla[ob] = mla - 0.5f;
        g_ppr[ob] = pp  - 0.5f;
    }
}

// ---------------------------------------------------------------------------
// Kernel 2: lag-correlation pass (unchanged from R15; correct, rel_err 0.0).
// ---------------------------------------------------------------------------
__global__ __launch_bounds__(256, 2) void gram_kernel()
{
    int b    = blockIdx.x;
    int nc   = b / NBANDS;
    int band = b - nc * NBANDS;
    int y0   = band * RB;
    int rowsThis = min(RB, PH - y0);

    __shared__ float sLa[(RB+2)*GSTR];
    __shared__ float sPr[(RB+2)*GSTR];
    __shared__ float wred[8][56];

    int t = threadIdx.x;
    size_t off = (size_t)nc * IMG;

    for (int q = t; q < (RB+2)*GSTR; q += 256) {
        int rr = q / GSTR, c = q - rr * GSTR;
        int u = y0 + rr, v = c - 2;
        float lv = 0.0f, pv = 0.0f;
        if (u < PH && (unsigned)v < (unsigned)PW) {
            lv = g_pla[off + (size_t)u*PW + v];
            pv = g_ppr[off + (size_t)u*PW + v];
        }
        sLa[q] = lv; sPr[q] = pv;
    }
    __syncthreads();

    ull   AK[13];
    float F[13], Rv[12];
    ull   S2 = 0ull;
    #pragma unroll
    for (int k = 0; k < 13; k++) { AK[k] = 0ull; F[k] = 0.0f; }
    #pragma unroll
    for (int k = 0; k < 12; k++) Rv[k] = 0.0f;

    int total = rowsThis * 43;
    for (int idx = t; idx < total; idx += 256) {
        int row = idx / 43;
        int run = idx - row * 43;
        int cb  = run * 4;

        float lc[4], pc[4];
        ull X[4];
        {
            float4 A = *(const float4*)&sLa[row*GSTR + cb];
            float4 B = *(const float4*)&sLa[row*GSTR + cb + 4];
            float4 C = *(const float4*)&sPr[row*GSTR + cb];
            float4 D = *(const float4*)&sPr[row*GSTR + cb + 4];
            float la0[8] = {A.x,A.y,A.z,A.w,B.x,B.y,B.z,B.w};
            float pr0[8] = {C.x,C.y,C.z,C.w,D.x,D.y,D.z,D.w};
            ull NP[8];
            #pragma unroll
            for (int q = 0; q < 8; q++) NP[q] = pk2(la0[q], pr0[q]);
            #pragma unroll
            for (int p = 0; p < 4; p++) {
                lc[p] = la0[2+p]; pc[p] = pr0[2+p];
                X[p] = NP[2+p];
                add2(S2, X[p]);
                fma2(AK[0], X[p], NP[2+p]);
                fma2(AK[1], X[p], NP[3+p]);
                fma2(AK[2], X[p], NP[4+p]);
                F[0]  += lc[p] * pr0[2+p];
                F[1]  += lc[p] * pr0[3+p];
                F[2]  += lc[p] * pr0[4+p];
                Rv[0] += pc[p] * la0[3+p];
                Rv[1] += pc[p] * la0[4+p];
            }
        }
        #pragma unroll
        for (int rr = 1; rr < 3; rr++) {
            float4 A = *(const float4*)&sLa[(row+rr)*GSTR + cb];
            float4 B = *(const float4*)&sLa[(row+rr)*GSTR + cb + 4];
            float4 C = *(const float4*)&sPr[(row+rr)*GSTR + cb];
            float4 D = *(const float4*)&sPr[(row+rr)*GSTR + cb + 4];
            float lar[8] = {A.x,A.y,A.z,A.w,B.x,B.y,B.z,B.w};
            float prr[8] = {C.x,C.y,C.z,C.w,D.x,D.y,D.z,D.w};
            ull NP[8];
            #pragma unroll
            for (int q = 0; q < 8; q++) NP[q] = pk2(lar[q], prr[q]);
            int kb = (rr == 1) ? 3 : 8;
            #pragma unroll
            for (int bb = 0; bb < 5; bb++) {
                int k = kb + bb;
                #pragma unroll
                for (int p = 0; p < 4; p++) {
                    fma2(AK[k], X[p], NP[p+bb]);
                    F[k]    += lc[p] * prr[p+bb];
                    Rv[k-1] += pc[p] * lar[p+bb];
                }
            }
        }
    }

    #pragma unroll
    for (int k = 0; k < 13; k++) {
        ull v = AK[k];
        #pragma unroll
        for (int o = 16; o; o >>= 1) { ull w = __shfl_xor_sync(0xffffffffu, v, o); add2(v, w); }
        AK[k] = v;
    }
    {
        ull v = S2;
        #pragma unroll
        for (int o = 16; o; o >>= 1) { ull w = __shfl_xor_sync(0xffffffffu, v, o); add2(v, w); }
        S2 = v;
    }
    #pragma unroll
    for (int k = 0; k < 13; k++) {
        float v = F[k];
        #pragma unroll
        for (int o = 16; o; o >>= 1) v += __shfl_xor_sync(0xffffffffu, v, o);
        F[k] = v;
    }
    #pragma unroll
    for (int k = 0; k < 12; k++) {
        float v = Rv[k];
        #pragma unroll
        for (int o = 16; o; o >>= 1) v += __shfl_xor_sync(0xffffffffu, v, o);
        Rv[k] = v;
    }

    int warp = t >> 5, lane = t & 31;
    if (lane == 0) {
        #pragma unroll
        for (int k = 0; k < 13; k++) {
            float ll, pp; upk2(AK[k], ll, pp);
            wred[warp][k]      = ll;
            wred[warp][13 + k] = pp;
            wred[warp][26 + k] = F[k];
        }
        #pragma unroll
        for (int k = 0; k < 12; k++) wred[warp][39 + k] = Rv[k];
        float sl, sp; upk2(S2, sl, sp);
        wred[warp][51] = sl; wred[warp][52] = sp;
    }
    __syncthreads();
    if (t < 53) {
        float s = 0.0f;
        #pragma unroll
        for (int w = 0; w < 8; w++) s += wred[w][t];
        g_part2[(size_t)b * 64 + t] = s;
    }
}

// ---------------------------------------------------------------------------
// Kernel 3: assemble Gram entries (T - corrections), corrections read from
// SMEM-STAGED boundary strips (rows/cols {0..3,165..170}), then 9x9 fp64
// solve. Last block folds the final reduction.
// ---------------------------------------------------------------------------
__global__ __launch_bounds__(192) void solve_kernel(float* __restrict__ out)
{
    __shared__ float  T2[64];
    __shared__ float  sRow[2][10*171];   // [plane][rmap(u)*171 + v]
    __shared__ float  sCol[2][171*10];   // [plane][u*10 + rmap(v)]
    __shared__ double Sred[192];
    __shared__ double A[81], La[81], W[81], Bm[81], sv[18];
    __shared__ double sm[128];
    __shared__ bool   isLast;

    int t = threadIdx.x, b = blockIdx.x;
    size_t off = (size_t)b * IMG;

    if (t < 53) {
        float s = 0.0f;
        #pragma unroll
        for (int p = 0; p < NBANDS; p++)
            s += g_part2[(size_t)(b*NBANDS + p) * 64 + t];
        T2[t] = s;
    }
    // stage boundary strips (both planes)
    for (int i = t; i < 10*171; i += 192) {
        int r = i / 171, v = i - r*171;
        int u = (r < 4) ? r : r + 161;
        sRow[0][i] = g_pla[off + (size_t)u*PW + v];
        sRow[1][i] = g_ppr[off + (size_t)u*PW + v];
    }
    for (int i = t; i < 171*10; i += 192) {
        int u = i / 10, ci = i - u*10;
        int v = (ci < 4) ? ci : ci + 161;
        sCol[0][i] = g_pla[off + (size_t)u*PW + v];
        sCol[1][i] = g_ppr[off + (size_t)u*PW + v];
    }
    __syncthreads();

    if (t < 171) {
        // decode upper-tri entry (i,j), i <= j
        int i = 0, rem = t;
        while (rem >= 18 - i) { rem -= 18 - i; i++; }
        int j = i + rem;
        int vi = (i < 9) ? i : i - 9;
        int vj = (j < 9) ? j : j - 9;
        int pi = (i < 9) ? 0 : 1;
        int pj = (j < 9) ? 0 : 1;
        int dyi = vi / 3, dxi = vi % 3;
        int dyj = vj / 3, dxj = vj % 3;
        int a = dyj - dyi, bb = dxj - dxi;

        float base;
        if (pi == 0 && pj == 0)      base = T2[lag_k(a, bb)];
        else if (pi == 1)            base = T2[13 + lag_k(a, bb)];
        else {
            bool canon = (a > 0) || (a == 0 && bb >= 0);
            base = canon ? T2[26 + lag_k(a, bb)]
                         : T2[39 + lag_k(-a, -bb) - 1];
        }

        const float* Rx = sRow[pi]; const float* Ry = sRow[pj];
        const float* Cx = sCol[pi]; const float* Cy = sCol[pj];
        int U0 = max(0, -a),  U1 = PH - max(a, 0);
        int V0 = max(0, -bb), V1 = PH - max(bb, 0);
        int RU0 = dyi, RU1 = dyi + NY;
        int RV0 = dxi, RV1 = dxi + NX;
        double c0 = 0.0, c1 = 0.0;
        // row strips: u in [U0,RU0) and [RU1,U1); u, u+a in row-strip set
        for (int u = U0; u < RU0; u++) {
            const float* px = Rx + rmap(u)*171;
            const float* py = Ry + rmap(u + a)*171 + bb;
            for (int v = V0; v < V1; v += 2) {
                c0 += (double)px[v] * (double)py[v];
                if (v + 1 < V1) c1 += (double)px[v+1] * (double)py[v+1];
            }
        }
        for (int u = RU1; u < U1; u++) {
            const float* px = Rx + rmap(u)*171;
            const float* py = Ry + rmap(u + a)*171 + bb;
            for (int v = V0; v < V1; v += 2) {
                c0 += (double)px[v] * (double)py[v];
                if (v + 1 < V1) c1 += (double)px[v+1] * (double)py[v+1];
            }
        }
        // col strips: v in [V0,RV0) and [RV1,V1); v, v+bb in col-strip set
        for (int v = RV0 - 1; v >= V0; v--) {
            int cx = rmap(v), cy = rmap(v + bb);
            for (int u = RU0; u < RU1; u += 2) {
                c0 += (double)Cx[u*10 + cx] * (double)Cy[(u + a)*10 + cy];
                if (u + 1 < RU1)
                    c1 += (double)Cx[(u+1)*10 + cx] * (double)Cy[(u+1+a)*10 + cy];
            }
        }
        for (int v = RV1; v < V1; v++) {
            int cx = rmap(v), cy = rmap(v + bb);
            for (int u = RU0; u < RU1; u += 2) {
                c0 += (double)Cx[u*10 + cx] * (double)Cy[(u + a)*10 + cy];
                if (u + 1 < RU1)
                    c1 += (double)Cx[(u+1)*10 + cx] * (double)Cy[(u+1+a)*10 + cy];
            }
        }
        Sred[t] = (double)base - c0 - c1;
    } else if (t < 189) {
        // view sums: s_I = full-plane sum - strips outside R_I
        int I = t - 171;
        int vi = (I < 9) ? I : I - 9;
        int pI = (I < 9) ? 0 : 1;
        int dyi = vi / 3, dxi = vi % 3;
        const float* Rx = sRow[pI];
        const float* Cx = sCol[pI];
        double c0 = 0.0, c1 = 0.0;
        for (int u = 0; u < dyi; u++) {
            const float* px = Rx + rmap(u)*171;
            for (int v = 0; v < PW; v += 2) {
                c0 += (double)px[v];
                if (v + 1 < PW) c1 += (double)px[v+1];
            }
        }
        for (int u = dyi + NY; u < PH; u++) {
            const float* px = Rx + rmap(u)*171;
            for (int v = 0; v < PW; v += 2) {
                c0 += (double)px[v];
                if (v + 1 < PW) c1 += (double)px[v+1];
            }
        }
        for (int v = 0; v < dxi; v++) {
            int cx = rmap(v);
            for (int u = dyi; u < dyi + NY; u += 2) {
                c0 += (double)Cx[u*10 + cx];
                if (u + 1 < dyi + NY) c1 += (double)Cx[(u+1)*10 + cx];
            }
        }
        for (int v = dxi + NX; v < PW; v++) {
            int cx = rmap(v);
            for (int u = dyi; u < dyi + NY; u += 2) {
                c0 += (double)Cx[u*10 + cx];
                if (u + 1 < dyi + NY) c1 += (double)Cx[(u+1)*10 + cx];
            }
        }
        Sred[t] = (double)T2[51 + pI] - c0 - c1;
    }
    __syncthreads();

    if (t < 18) sv[t] = Sred[171 + t];
    __syncthreads();

    const double invM = 1.0 / (double)MTOT;
    if (t < 81) {
        int d = t / 9, e = t % 9;
        int i, j;
        i = 9 + d; j = 9 + e; if (i > j) { int q = i; i = j; j = q; }
        A[t]  = Sred[tri_idx(i, j)] - sv[9+d]*sv[9+e]*invM + (d == e ? 1e-3 : 0.0);
        i = d; j = e; if (i > j) { int q = i; i = j; j = q; }
        La[t] = Sred[tri_idx(i, j)] - sv[d]*sv[e]*invM;
        W[t]  = Sred[tri_idx(e, 9 + d)] - sv[e]*sv[9+d]*invM;
    }
    __syncthreads();

    if (t < 32) {
        #pragma unroll 1
        for (int j = 0; j < 9; j++) {
            if (t == 0) {
                double dd = A[j*9 + j];
                for (int k = 0; k < j; k++) dd -= A[j*9 + k]*A[j*9 + k];
                A[j*9 + j] = sqrt(fmax(dd, 1e-300));
            }
            __syncwarp();
            if (t > j && t < 9) {
                double v = A[t*9 + j];
                for (int k = 0; k < j; k++) v -= A[t*9 + k]*A[j*9 + k];
                A[t*9 + j] = v / A[j*9 + j];
            }
            __syncwarp();
        }
        #pragma unroll 1
        for (int f = 0; f < 9; f++) {
            if (t < 9) {
                double v = W[f*9 + t];
                for (int k = 0; k < f; k++) v -= A[f*9 + k]*W[k*9 + t];
                W[f*9 + t] = v / A[f*9 + f];
            }
            __syncwarp();
        }
    }
    __syncthreads();

    if (t < 81) {
        int d = t / 9, g = t % 9;
        double v = La[t];
        #pragma unroll
        for (int f = 0; f < 9; f++) v -= W[f*9 + d]*W[f*9 + g];
        Bm[t] = v + (d == g ? 1e-3 : 0.0);
    }
    __syncthreads();

    if (t < 32) {
        #pragma unroll 1
        for (int j = 0; j < 9; j++) {
            if (t == 0) {
                double dd = Bm[j*9 + j];
                for (int k = 0; k < j; k++) dd -= Bm[j*9 + k]*Bm[j*9 + k];
                Bm[j*9 + j] = sqrt(fmax(dd, 1e-300));
            }
            __syncwarp();
            if (t > j && t < 9) {
                double v = Bm[t*9 + j];
                for (int k = 0; k < j; k++) v -= Bm[t*9 + k]*Bm[j*9 + k];
                Bm[t*9 + j] = v / Bm[j*9 + j];
            }
            __syncwarp();
        }
        if (t == 0) {
            double r = 0.0;
            for (int j = 0; j < 9; j++) r += log(Bm[j*9 + j] + 1e-8);
            g_rmi[b] = r;
        }
    }
    __syncthreads();

    if (t == 0) {
        __threadfence();
        int old = atomicAdd(&g_cnt, 1);
        isLast = (old == NC - 1);
    }
    __syncthreads();
    if (isLast) {
        __threadfence();
        if (t < 128) sm[t] = (t < NC) ? g_rmi[t] : 0.0;
        __syncthreads();
        #pragma unroll
        for (int s = 64; s; s >>= 1) {
            if (t < s) sm[t] += sm[t + s];
            __syncthreads();
        }
        if (t == 0) {
            out[0] = (float)(sm[0] / 36.0);
            g_cnt = 0;
        }
    }
}

// ---------------------------------------------------------------------------
extern "C" void kernel_launch(void* const* d_in, const int* in_sizes, int n_in,
                              void* d_out, int out_size)
{
    const float* cls   = (const float*)d_in[0];
    const float* tgt   = (const float*)d_in[1];
    const float* valid = (const float*)d_in[2];

    dim3 pg((PH + PRB - 1) / PRB, NC);
    pool_kernel<<<pg, 256>>>(cls, tgt, valid);
    gram_kernel<<<NC*NBANDS, 256>>>();
    solve_kernel<<<NC, 192>>>((float*)d_out);
}

// round 17
// speedup vs baseline: 2.7932x; 2.7932x over previous
#include <cuda_runtime.h>
#include <math.h>

#define NN 4
#define CC 26
#define NC 104
#define HH 512
#define WW 512
#define PH 171
#define PW 171
#define IMG (PH*PW)     // 29241
#define NY 169
#define NX 169
#define MTOT (NY*NX)
#define PRB 2           // pool: output rows per block
#define RSTR 520        // pool: smem row stride (4 pad + 512 + 4)
#define RB 29           // gram: image rows per band
#define NBANDS 6        // ceil(171/29)
#define GSTR 176        // gram smem col stride (2 pad + 171 + 3 pad)

typedef unsigned long long ull;

// scratch (static device arrays; no runtime allocation)
__device__ float g_pla[NC*IMG];        // pooled labels, SHIFTED by -0.5
__device__ float g_ppr[NC*IMG];        // pooled probs,  SHIFTED by -0.5
__device__ float g_part2[NC*NBANDS*64];// per-band lag partials (53 used)
__device__ double g_rmi[NC];
__device__ int    g_cnt = 0;

// ---- f32x2 packed helpers (sm_103a FFMA2 via PTX) -------------------------
__device__ __forceinline__ ull pk2(float lo, float hi) {
    ull r; asm("mov.b64 %0,{%1,%2};" : "=l"(r) : "f"(lo), "f"(hi)); return r;
}
__device__ __forceinline__ void fma2(ull& acc, ull a, ull b) {
    asm("fma.rn.f32x2 %0,%1,%2,%0;" : "+l"(acc) : "l"(a), "l"(b));
}
__device__ __forceinline__ void add2(ull& acc, ull v) {
    asm("add.rn.f32x2 %0,%1,%0;" : "+l"(acc) : "l"(v));
}
__device__ __forceinline__ void upk2(ull v, float& lo, float& hi) {
    asm("mov.b64 {%0,%1},%2;" : "=f"(lo), "=f"(hi) : "l"(v));
}
__device__ __forceinline__ int tri_idx(int i, int j)  // i <= j, 18x18 upper tri
{
    return i*18 - (i*(i-1))/2 + (j - i);
}
// canonical lag list (a,b): a=0:b in 0..2 -> k=b; a=1:b in -2..2 -> k=5+b; a=2 -> k=10+b
__device__ __forceinline__ int lag_k(int a, int b)
{
    return (a == 0) ? b : ((a == 1) ? 5 + b : 10 + b);
}
// strip index maps (valid only for u/v in {0..3} U {165..170})
__device__ __forceinline__ int rmap(int u) { return (u < 4) ? u : u - 161; }

// ---------------------------------------------------------------------------
// Kernel 1: mask + sigmoid + 3x3/stride3 max-pool, smem-staged.
// Writes planes shifted by -0.5 (covariances are shift-invariant).
// ---------------------------------------------------------------------------
__global__ __launch_bounds__(256) void pool_kernel(const float* __restrict__ cls,
                                                   const float* __restrict__ tgt,
                                                   const float* __restrict__ valid)
{
    int nc  = blockIdx.y;
    int n   = nc / CC;
    int py0 = blockIdx.x * PRB;
    int t   = threadIdx.x;

    __shared__ float sT[6*RSTR];
    __shared__ float sX[6*RSTR];

    const float* cb = cls   + (size_t)nc * HH * WW;
    const float* tb = tgt   + (size_t)nc * HH * WW;
    const float* vb = valid + (size_t)n  * HH * WW;

    const float BIG = -3.0e38f;

    for (int q = t; q < 6*128; q += 256) {
        int i = q >> 7;
        int k = q & 127;
        int r = 3*py0 - 1 + i;
        float4 T4, X4;
        if ((unsigned)r < (unsigned)HH) {
            float4 c = ((const float4*)(cb + (size_t)r*WW))[k];
            float4 g = ((const float4*)(tb + (size_t)r*WW))[k];
            float4 v = ((const float4*)(vb + (size_t)r*WW))[k];
            T4.x = g.x*v.x; T4.y = g.y*v.y; T4.z = g.z*v.z; T4.w = g.w*v.w;
            X4.x = v.x > 0.0f ? c.x : BIG;
            X4.y = v.y > 0.0f ? c.y : BIG;
            X4.z = v.z > 0.0f ? c.z : BIG;
            X4.w = v.w > 0.0f ? c.w : BIG;
        } else {
            T4.x = T4.y = T4.z = T4.w = 0.0f;
            X4.x = X4.y = X4.z = X4.w = BIG;
        }
        *(float4*)&sT[i*RSTR + 4 + 4*k] = T4;
        *(float4*)&sX[i*RSTR + 4 + 4*k] = X4;
    }
    if (t < 6) { sT[t*RSTR + 3] = 0.0f; sX[t*RSTR + 3] = BIG; }
    __syncthreads();

    for (int o = t; o < PRB*PW; o += 256) {
        int pyl = o / PW, px = o - pyl*PW;
        int py  = py0 + pyl;
        if (py >= PH) continue;
        int base = pyl*3*RSTR + 3 + 3*px;
        float mla = 0.0f, mx = BIG;
        #pragma unroll
        for (int rr = 0; rr < 3; rr++) {
            int bb = base + rr*RSTR;
            #pragma unroll
            for (int cc = 0; cc < 3; cc++) {
                mla = fmaxf(mla, sT[bb + cc]);
                mx  = fmaxf(mx,  sX[bb + cc]);
            }
        }
        float pp = 1.0f/(1.0f + __expf(-mx)) + 1e-6f;
        size_t ob = (size_t)nc * IMG + (size_t)py*PW + px;
        g_pla[ob] = mla - 0.5f;
        g_ppr[ob] = pp  - 0.5f;
    }
}

// ---------------------------------------------------------------------------
// Kernel 2: lag-correlation pass. CHANGE vs R16: __launch_bounds__(256,1) —
// release the 128-reg cap (live set ~130 regs was spilling at occ 2).
// ---------------------------------------------------------------------------
__global__ __launch_bounds__(256, 1) void gram_kernel()
{
    int b    = blockIdx.x;
    int nc   = b / NBANDS;
    int band = b - nc * NBANDS;
    int y0   = band * RB;
    int rowsThis = min(RB, PH - y0);

    __shared__ float sLa[(RB+2)*GSTR];
    __shared__ float sPr[(RB+2)*GSTR];
    __shared__ float wred[8][56];

    int t = threadIdx.x;
    size_t off = (size_t)nc * IMG;

    for (int q = t; q < (RB+2)*GSTR; q += 256) {
        int rr = q / GSTR, c = q - rr * GSTR;
        int u = y0 + rr, v = c - 2;
        float lv = 0.0f, pv = 0.0f;
        if (u < PH && (unsigned)v < (unsigned)PW) {
            lv = g_pla[off + (size_t)u*PW + v];
            pv = g_ppr[off + (size_t)u*PW + v];
        }
        sLa[q] = lv; sPr[q] = pv;
    }
    __syncthreads();

    ull   AK[13];
    float F[13], Rv[12];
    ull   S2 = 0ull;
    #pragma unroll
    for (int k = 0; k < 13; k++) { AK[k] = 0ull; F[k] = 0.0f; }
    #pragma unroll
    for (int k = 0; k < 12; k++) Rv[k] = 0.0f;

    int total = rowsThis * 43;
    for (int idx = t; idx < total; idx += 256) {
        int row = idx / 43;
        int run = idx - row * 43;
        int cb  = run * 4;

        float lc[4], pc[4];
        ull X[4];
        {
            float4 A = *(const float4*)&sLa[row*GSTR + cb];
            float4 B = *(const float4*)&sLa[row*GSTR + cb + 4];
            float4 C = *(const float4*)&sPr[row*GSTR + cb];
            float4 D = *(const float4*)&sPr[row*GSTR + cb + 4];
            float la0[8] = {A.x,A.y,A.z,A.w,B.x,B.y,B.z,B.w};
            float pr0[8] = {C.x,C.y,C.z,C.w,D.x,D.y,D.z,D.w};
            ull NP[8];
            #pragma unroll
            for (int q = 0; q < 8; q++) NP[q] = pk2(la0[q], pr0[q]);
            #pragma unroll
            for (int p = 0; p < 4; p++) {
                lc[p] = la0[2+p]; pc[p] = pr0[2+p];
                X[p] = NP[2+p];
                add2(S2, X[p]);
                fma2(AK[0], X[p], NP[2+p]);
                fma2(AK[1], X[p], NP[3+p]);
                fma2(AK[2], X[p], NP[4+p]);
                F[0]  += lc[p] * pr0[2+p];
                F[1]  += lc[p] * pr0[3+p];
                F[2]  += lc[p] * pr0[4+p];
                Rv[0] += pc[p] * la0[3+p];
                Rv[1] += pc[p] * la0[4+p];
            }
        }
        #pragma unroll
        for (int rr = 1; rr < 3; rr++) {
            float4 A = *(const float4*)&sLa[(row+rr)*GSTR + cb];
            float4 B = *(const float4*)&sLa[(row+rr)*GSTR + cb + 4];
            float4 C = *(const float4*)&sPr[(row+rr)*GSTR + cb];
            float4 D = *(const float4*)&sPr[(row+rr)*GSTR + cb + 4];
            float lar[8] = {A.x,A.y,A.z,A.w,B.x,B.y,B.z,B.w};
            float prr[8] = {C.x,C.y,C.z,C.w,D.x,D.y,D.z,D.w};
            ull NP[8];
            #pragma unroll
            for (int q = 0; q < 8; q++) NP[q] = pk2(lar[q], prr[q]);
            int kb = (rr == 1) ? 3 : 8;
            #pragma unroll
            for (int bb = 0; bb < 5; bb++) {
                int k = kb + bb;
                #pragma unroll
                for (int p = 0; p < 4; p++) {
                    fma2(AK[k], X[p], NP[p+bb]);
                    F[k]    += lc[p] * prr[p+bb];
                    Rv[k-1] += pc[p] * lar[p+bb];
                }
            }
        }
    }

    #pragma unroll
    for (int k = 0; k < 13; k++) {
        ull v = AK[k];
        #pragma unroll
        for (int o = 16; o; o >>= 1) { ull w = __shfl_xor_sync(0xffffffffu, v, o); add2(v, w); }
        AK[k] = v;
    }
    {
        ull v = S2;
        #pragma unroll
        for (int o = 16; o; o >>= 1) { ull w = __shfl_xor_sync(0xffffffffu, v, o); add2(v, w); }
        S2 = v;
    }
    #pragma unroll
    for (int k = 0; k < 13; k++) {
        float v = F[k];
        #pragma unroll
        for (int o = 16; o; o >>= 1) v += __shfl_xor_sync(0xffffffffu, v, o);
        F[k] = v;
    }
    #pragma unroll
    for (int k = 0; k < 12; k++) {
        float v = Rv[k];
        #pragma unroll
        for (int o = 16; o; o >>= 1) v += __shfl_xor_sync(0xffffffffu, v, o);
        Rv[k] = v;
    }

    int warp = t >> 5, lane = t & 31;
    if (lane == 0) {
        #pragma unroll
        for (int k = 0; k < 13; k++) {
            float ll, pp; upk2(AK[k], ll, pp);
            wred[warp][k]      = ll;
            wred[warp][13 + k] = pp;
            wred[warp][26 + k] = F[k];
        }
        #pragma unroll
        for (int k = 0; k < 12; k++) wred[warp][39 + k] = Rv[k];
        float sl, sp; upk2(S2, sl, sp);
        wred[warp][51] = sl; wred[warp][52] = sp;
    }
    __syncthreads();
    if (t < 53) {
        float s = 0.0f;
        #pragma unroll
        for (int w = 0; w < 8; w++) s += wred[w][t];
        g_part2[(size_t)b * 64 + t] = s;
    }
}

// ---------------------------------------------------------------------------
// Kernel 3: assemble Gram entries (T - corrections), corrections from
// smem-staged boundary strips, accumulated in FP32 4-chain (vs fp64 chains)
// — removes any dependence on GB300's cut FP64 rate. Then 9x9 fp64 solve.
// ---------------------------------------------------------------------------
__global__ __launch_bounds__(192) void solve_kernel(float* __restrict__ out)
{
    __shared__ float  T2[64];
    __shared__ float  sRow[2][10*171];   // [plane][rmap(u)*171 + v]
    __shared__ float  sCol[2][171*10];   // [plane][u*10 + rmap(v)]
    __shared__ double Sred[192];
    __shared__ double A[81], La[81], W[81], Bm[81], sv[18];
    __shared__ double sm[128];
    __shared__ bool   isLast;

    int t = threadIdx.x, b = blockIdx.x;
    size_t off = (size_t)b * IMG;

    if (t < 53) {
        float s = 0.0f;
        #pragma unroll
        for (int p = 0; p < NBANDS; p++)
            s += g_part2[(size_t)(b*NBANDS + p) * 64 + t];
        T2[t] = s;
    }
    for (int i = t; i < 10*171; i += 192) {
        int r = i / 171, v = i - r*171;
        int u = (r < 4) ? r : r + 161;
        sRow[0][i] = g_pla[off + (size_t)u*PW + v];
        sRow[1][i] = g_ppr[off + (size_t)u*PW + v];
    }
    for (int i = t; i < 171*10; i += 192) {
        int u = i / 10, ci = i - u*10;
        int v = (ci < 4) ? ci : ci + 161;
        sCol[0][i] = g_pla[off + (size_t)u*PW + v];
        sCol[1][i] = g_ppr[off + (size_t)u*PW + v];
    }
    __syncthreads();

    if (t < 171) {
        int i = 0, rem = t;
        while (rem >= 18 - i) { rem -= 18 - i; i++; }
        int j = i + rem;
        int vi = (i < 9) ? i : i - 9;
        int vj = (j < 9) ? j : j - 9;
        int pi = (i < 9) ? 0 : 1;
        int pj = (j < 9) ? 0 : 1;
        int dyi = vi / 3, dxi = vi % 3;
        int dyj = vj / 3, dxj = vj % 3;
        int a = dyj - dyi, bb = dxj - dxi;

        float base;
        if (pi == 0 && pj == 0)      base = T2[lag_k(a, bb)];
        else if (pi == 1)            base = T2[13 + lag_k(a, bb)];
        else {
            bool canon = (a > 0) || (a == 0 && bb >= 0);
            base = canon ? T2[26 + lag_k(a, bb)]
                         : T2[39 + lag_k(-a, -bb) - 1];
        }

        const float* Rx = sRow[pi]; const float* Ry = sRow[pj];
        const float* Cx = sCol[pi]; const float* Cy = sCol[pj];
        int U0 = max(0, -a),  U1 = PH - max(a, 0);
        int V0 = max(0, -bb), V1 = PH - max(bb, 0);
        int RU0 = dyi, RU1 = dyi + NY;
        int RV0 = dxi, RV1 = dxi + NX;
        float c0 = 0.0f, c1 = 0.0f, c2 = 0.0f, c3 = 0.0f;
        for (int u = U0; u < RU0; u++) {
            const float* px = Rx + rmap(u)*171;
            const float* py = Ry + rmap(u + a)*171 + bb;
            for (int v = V0; v < V1; v += 2) {
                c0 += px[v] * py[v];
                if (v + 1 < V1) c1 += px[v+1] * py[v+1];
            }
        }
        for (int u = RU1; u < U1; u++) {
            const float* px = Rx + rmap(u)*171;
            const float* py = Ry + rmap(u + a)*171 + bb;
            for (int v = V0; v < V1; v += 2) {
                c0 += px[v] * py[v];
                if (v + 1 < V1) c1 += px[v+1] * py[v+1];
            }
        }
        for (int v = RV0 - 1; v >= V0; v--) {
            int cx = rmap(v), cy = rmap(v + bb);
            for (int u = RU0; u < RU1; u += 2) {
                c2 += Cx[u*10 + cx] * Cy[(u + a)*10 + cy];
                if (u + 1 < RU1)
                    c3 += Cx[(u+1)*10 + cx] * Cy[(u+1+a)*10 + cy];
            }
        }
        for (int v = RV1; v < V1; v++) {
            int cx = rmap(v), cy = rmap(v + bb);
            for (int u = RU0; u < RU1; u += 2) {
                c2 += Cx[u*10 + cx] * Cy[(u + a)*10 + cy];
                if (u + 1 < RU1)
                    c3 += Cx[(u+1)*10 + cx] * Cy[(u+1+a)*10 + cy];
            }
        }
        Sred[t] = (double)base - ((double)c0 + (double)c1 + (double)c2 + (double)c3);
    } else if (t < 189) {
        int I = t - 171;
        int vi = (I < 9) ? I : I - 9;
        int pI = (I < 9) ? 0 : 1;
        int dyi = vi / 3, dxi = vi % 3;
        const float* Rx = sRow[pI];
        const float* Cx = sCol[pI];
        float c0 = 0.0f, c1 = 0.0f, c2 = 0.0f, c3 = 0.0f;
        for (int u = 0; u < dyi; u++) {
            const float* px = Rx + rmap(u)*171;
            for (int v = 0; v < PW; v += 2) {
                c0 += px[v];
                if (v + 1 < PW) c1 += px[v+1];
            }
        }
        for (int u = dyi + NY; u < PH; u++) {
            const float* px = Rx + rmap(u)*171;
            for (int v = 0; v < PW; v += 2) {
                c0 += px[v];
                if (v + 1 < PW) c1 += px[v+1];
            }
        }
        for (int v = 0; v < dxi; v++) {
            int cx = rmap(v);
            for (int u = dyi; u < dyi + NY; u += 2) {
                c2 += Cx[u*10 + cx];
                if (u + 1 < dyi + NY) c3 += Cx[(u+1)*10 + cx];
            }
        }
        for (int v = dxi + NX; v < PW; v++) {
            int cx = rmap(v);
            for (int u = dyi; u < dyi + NY; u += 2) {
                c2 += Cx[u*10 + cx];
                if (u + 1 < dyi + NY) c3 += Cx[(u+1)*10 + cx];
            }
        }
        Sred[t] = (double)T2[51 + pI] - ((double)c0 + (double)c1 + (double)c2 + (double)c3);
    }
    __syncthreads();

    if (t < 18) sv[t] = Sred[171 + t];
    __syncthreads();

    const double invM = 1.0 / (double)MTOT;
    if (t < 81) {
        int d = t / 9, e = t % 9;
        int i, j;
        i = 9 + d; j = 9 + e; if (i > j) { int q = i; i = j; j = q; }
        A[t]  = Sred[tri_idx(i, j)] - sv[9+d]*sv[9+e]*invM + (d == e ? 1e-3 : 0.0);
        i = d; j = e; if (i > j) { int q = i; i = j; j = q; }
        La[t] = Sred[tri_idx(i, j)] - sv[d]*sv[e]*invM;
        W[t]  = Sred[tri_idx(e, 9 + d)] - sv[e]*sv[9+d]*invM;
    }
    __syncthreads();

    if (t < 32) {
        #pragma unroll 1
        for (int j = 0; j < 9; j++) {
            if (t == 0) {
                double dd = A[j*9 + j];
                for (int k = 0; k < j; k++) dd -= A[j*9 + k]*A[j*9 + k];
                A[j*9 + j] = sqrt(fmax(dd, 1e-300));
            }
            __syncwarp();
            if (t > j && t < 9) {
                double v = A[t*9 + j];
                for (int k = 0; k < j; k++) v -= A[t*9 + k]*A[j*9 + k];
                A[t*9 + j] = v / A[j*9 + j];
            }
            __syncwarp();
        }
        #pragma unroll 1
        for (int f = 0; f < 9; f++) {
            if (t < 9) {
                double v = W[f*9 + t];
                for (int k = 0; k < f; k++) v -= A[f*9 + k]*W[k*9 + t];
                W[f*9 + t] = v / A[f*9 + f];
            }
            __syncwarp();
        }
    }
    __syncthreads();

    if (t < 81) {
        int d = t / 9, g = t % 9;
        double v = La[t];
        #pragma unroll
        for (int f = 0; f < 9; f++) v -= W[f*9 + d]*W[f*9 + g];
        Bm[t] = v + (d == g ? 1e-3 : 0.0);
    }
    __syncthreads();

    if (t < 32) {
        #pragma unroll 1
        for (int j = 0; j < 9; j++) {
            if (t == 0) {
                double dd = Bm[j*9 + j];
                for (int k = 0; k < j; k++) dd -= Bm[j*9 + k]*Bm[j*9 + k];
                Bm[j*9 + j] = sqrt(fmax(dd, 1e-300));
            }
            __syncwarp();
            if (t > j && t < 9) {
                double v = Bm[t*9 + j];
                for (int k = 0; k < j; k++) v -= Bm[t*9 + k]*Bm[j*9 + k];
                Bm[t*9 + j] = v / Bm[j*9 + j];
            }
            __syncwarp();
        }
        if (t == 0) {
            double r = 0.0;
            for (int j = 0; j < 9; j++) r += log(Bm[j*9 + j] + 1e-8);
            g_rmi[b] = r;
        }
    }
    __syncthreads();

    if (t == 0) {
        __threadfence();
        int old = atomicAdd(&g_cnt, 1);
        isLast = (old == NC - 1);
    }
    __syncthreads();
    if (isLast) {
        __threadfence();
        if (t < 128) sm[t] = (t < NC) ? g_rmi[t] : 0.0;
        __syncthreads();
        #pragma unroll
        for (int s = 64; s; s >>= 1) {
            if (t < s) sm[t] += sm[t + s];
            __syncthreads();
        }
        if (t == 0) {
            out[0] = (float)(sm[0] / 36.0);
            g_cnt = 0;
        }
    }
}

// ---------------------------------------------------------------------------
extern "C" void kernel_launch(void* const* d_in, const int* in_sizes, int n_in,
                              void* d_out, int out_size)
{
    const float* cls   = (const float*)d_in[0];
    const float* tgt   = (const float*)d_in[1];
    const float* valid = (const float*)d_in[2];

    dim3 pg((PH + PRB - 1) / PRB, NC);
    pool_kernel<<<pg, 256>>>(cls, tgt, valid);
    gram_kernel<<<NC*NBANDS, 256>>>();
    solve_kernel<<<NC, 192>>>((float*)d_out);
}